// round 15
// baseline (speedup 1.0000x reference)
#include <cuda_runtime.h>
#include <cuda_bf16.h>

#define NT      288
#define FEAT    144
#define YDIM    25
#define EDGE_R  4864
#define NPATH   19

// Per-path tables (enumeration order = reference loops)
__constant__ int c_lo[NPATH]    = {0,0,0,1,1,1,1,1,1,1,2,2,2,2,2,2,2,2,2};
__constant__ int c_li[NPATH]    = {0,1,2,0,1,1,1,2,2,2,0,1,1,1,2,2,2,2,2};
__constant__ int c_lf[NPATH]    = {0,1,2,1,0,1,2,1,2,3,2,1,2,3,0,1,2,3,4};
__constant__ int c_cgoff[NPATH] = {0,1,10,35,44,53,80,125,170,245,350,375,420,495,600,625,700,825,1000};
__constant__ int c_cyoff[NPATH] = {0,1,4,9,12,21,30,39,54,69,84,89,104,119,134,159,184,209,234};
__constant__ int c_cyrow[NPATH] = {0,1,2,3,6,9,12,15,18,21,24,29,34,39,44,49,54,59,64};
__constant__ int c_b2off[NPATH] = {0,16,32,48,96,144,192,240,288,336,384,464,544,624,704,784,864,944,1024};
__constant__ int c_pair[NPATH]  = {0,1,2,3,4,4,4,5,5,5,6,7,7,7,8,8,8,8,8};
__constant__ int c_k[NPATH]     = {0,0,0,0,0,1,2,0,1,2,0,0,1,2,0,1,2,3,4};
__constant__ int c_gw[9]        = {0,20,40,60,120,276,432,532,792};
__constant__ int c_nlf9[9]      = {1,1,1,1,3,3,1,3,5};
// padded-F geometry per li: base word, v-stride
__constant__ int c_fpoff[3]     = {0,16,80};
__constant__ int c_fpstr[3]     = {1,4,8};
// df-sorted B1 placement: rank = c_b1rank[p] + j  (sorted by lf asc, path asc)
__constant__ int c_b1rank[NPATH] = {0,35,105,38,1,41,110,50,119,179,134,65,139,194,10,80,154,209,234};

// Precomputed tables (static device memory)
__device__ unsigned int   g_b1p[259];    // dst<<20 | wb<<9 | stride<<3 | lf   (df-sorted order)
__device__ uint2          g_b2q[276];    // quad descs: {gdst | cyb<<11 | fb<<21, di | nlf<<3 | fstr<<6}
__device__ float          g_wcgT[1225];  // TRANSPOSED: per path, df planes of (do*di)
__device__ unsigned short g_rmap[1216];  // src f4 -> padded smem f4

__device__ __forceinline__ void cp_async16(unsigned int smem_addr, const void* gptr) {
    asm volatile("cp.async.cg.shared.global [%0], [%1], 16;"
                 :: "r"(smem_addr), "l"(gptr));
}

// Padded R layout per (lo,li) pair: 16 u-rows of (4*nlf+1) float4 each.
// Word stride 16nlf+4 == 20 (mod 32) -> conflict-free across u rows.
__device__ int map_r(int G4) {
    if (G4 < 256) { int r = G4 >> 6, l = G4 & 63; return r * 80 + (l >> 2) * 5 + (l & 3); }
    else if (G4 < 448) { int l = G4 - 256, u = l / 12; return 320 + u * 13 + (l - u * 12); }
    else if (G4 < 640) { int l = G4 - 448, u = l / 12; return 528 + u * 13 + (l - u * 12); }
    else if (G4 < 704) { int l = G4 - 640; return 736 + (l >> 2) * 5 + (l & 3); }
    else if (G4 < 896) { int l = G4 - 704, u = l / 12; return 816 + u * 13 + (l - u * 12); }
    else { int l = G4 - 896, u = l / 20; return 1024 + u * 21 + (l - u * 20); }
}

// prep: zero output + build all tables (O(paths) per thread, no sorting loops)
__global__ void prep_kernel(float* out, int n,
                            const float* __restrict__ cg, const float* __restrict__ W) {
    int t = blockIdx.x * blockDim.x + threadIdx.x;
    if (t < n) out[t] = 0.f;
    if (t < 259) {
        int p = 0;
        for (int q = 1; q < NPATH; ++q) if (t >= c_cyoff[q]) p = q;
        int j = t - c_cyoff[p];
        int li = c_li[p], lf = c_lf[p], lo = c_lo[p];
        int di = 2 * li + 1, doo = 2 * lo + 1;
        int o = j / di, i = j - o * di;
        unsigned dst = (unsigned)((c_cyrow[p] + o) * 8 + i);
        unsigned str = (unsigned)(doo * di);
        unsigned desc = (dst << 20) | ((unsigned)(c_cgoff[p] + j) << 9)
                      | (str << 3) | (unsigned)lf;
        g_b1p[c_b1rank[p] + j] = desc;      // df-sorted placement, O(1)
    }
    if (t < 276) {     // B2 quad descriptor: per path, (o, m) with m = v-group of 4
        int p = 0;
        for (int q = 1; q < NPATH; ++q) if (t >= (c_b2off[q] >> 2)) p = q;
        int j = t - (c_b2off[p] >> 2);
        int o = j >> 2, m = j & 3;
        int li = c_li[p], di = 2 * li + 1;
        int pr = c_pair[p], nlf = c_nlf9[pr];
        int fstr = c_fpstr[li];
        unsigned gdst = (unsigned)(c_gw[pr] + o * (16 * nlf + 4) + (4 * m) * nlf + c_k[p]);
        unsigned cyb  = (unsigned)((c_cyrow[p] + o) * 8);
        unsigned fb   = (unsigned)(c_fpoff[li] + (4 * m) * fstr);
        uint2 d;
        d.x = gdst | (cyb << 11) | (fb << 21);
        d.y = (unsigned)di | ((unsigned)nlf << 3) | ((unsigned)fstr << 6);
        g_b2q[t] = d;
    }
    if (t < 1225) {   // transposed W-folded cg
        int p = 0;
        for (int q = 1; q < NPATH; ++q) if (t >= c_cgoff[q]) p = q;
        int local = t - c_cgoff[p];
        int lo = c_lo[p], li = c_li[p], lf = c_lf[p];
        int n2 = (2 * lo + 1) * (2 * li + 1), df = 2 * lf + 1;
        int f = local / n2, j = local - f * n2;
        g_wcgT[t] = cg[c_cgoff[p] + j * df + f] * W[p];
    }
    if (t < 1216) g_rmap[t] = (unsigned short)map_r(t);
}

// acc += R_row . G_row over 4*NLF float4 from padded smem (conflict-free, broadcast-dedup)
template<int NLF>
__device__ __forceinline__ float pairdot_s(const float4* __restrict__ sR4,
                                           const float4* __restrict__ sG4,
                                           int rf4, int gf4, int u, int o) {
    const float4* r = sR4 + rf4 + u * (4 * NLF + 1);
    const float4* g = sG4 + gf4 + o * (4 * NLF + 1);
    float a0 = 0.f, a1 = 0.f, a2 = 0.f, a3 = 0.f;
    #pragma unroll
    for (int j = 0; j < 4 * NLF; ++j) {
        float4 A = r[j];
        float4 B = g[j];
        a0 = fmaf(A.x, B.x, a0);
        a1 = fmaf(A.y, B.y, a1);
        a2 = fmaf(A.z, B.z, a2);
        a3 = fmaf(A.w, B.w, a3);
    }
    return (a0 + a1) + (a2 + a3);
}

__global__ void __launch_bounds__(NT, 6)
tp_kernel(const float* __restrict__ feat, const float* __restrict__ rbf,
          const float* __restrict__ Y,    const int* __restrict__ aidx,
          const int* __restrict__ bidx,   float* __restrict__ out, int E)
{
    __shared__ float4 sR4[1360];     // padded R (21.8 KB)
    __shared__ float4 sG4[304];      // padded/interleaved W*G''
    __shared__ float4 sCY4[138];     // padded CY: 69 rows x 8 words
    __shared__ float4 sFp4[52];      // padded F: 208 words (li strides 1/4/8)
    __shared__ float  sY[32];

    float* sCY = reinterpret_cast<float*>(sCY4);
    float* sFp = reinterpret_cast<float*>(sFp4);

    const int e = blockIdx.x, tid = threadIdx.x;
    const int a = aidx[e];
    const int b = bidx[e];

    // ---- Phase A0: fire ALL R copies async (DRAM latency overlaps B1/B2) ----
    {
        const float4* r4 = reinterpret_cast<const float4*>(rbf + (size_t)e * EDGE_R);
        const unsigned int sR_base = (unsigned int)__cvta_generic_to_shared(sR4);
        #pragma unroll
        for (int i = 0; i < 5; ++i) {
            int t = tid + i * NT;
            if (t < 1216)
                cp_async16(sR_base + (unsigned)__ldg(&g_rmap[t]) * 16u, r4 + t);
        }
        asm volatile("cp.async.commit_group;");
    }

    // ---- Phase A1: F gather into PADDED layout + Y ----
    {
        const float* Fr = feat + (size_t)b * FEAT;
        if (tid < 208) {
            int w = tid;
            float val = 0.f;
            bool wr = true;
            if (w < 16) {
                val = __ldg(&Fr[w]);
            } else if (w < 80) {
                int v = (w - 16) >> 2, i = (w - 16) & 3;
                if (i < 3) val = __ldg(&Fr[16 + v * 3 + i]); else wr = false;
            } else {
                int v = (w - 80) >> 3, i = (w - 80) & 7;
                if (i < 5) val = __ldg(&Fr[64 + v * 5 + i]); else wr = false;
            }
            if (wr) sFp[w] = val;
        }
        if (tid >= 224 && tid < 224 + YDIM)
            sY[tid - 224] = __ldg(&Y[(size_t)e * YDIM + (tid - 224)]);
    }
    __syncthreads();

    // ---- Phase B1: CY[dst] = sum_f wcgT[wb + f*str] * Y[lf*lf+f]
    //      df-sorted order -> warps have uniform df, no max-df penalty ----
    if (tid < 259) {
        unsigned d = __ldg(&g_b1p[tid]);
        int lf = d & 7, str = (d >> 3) & 63, wb = (d >> 9) & 0x7FF, dst = d >> 20;
        int df = 2 * lf + 1, yb = lf * lf;
        float s = 0.f;
        for (int f = 0; f < df; ++f)
            s = fmaf(__ldg(&g_wcgT[wb + f * str]), sY[yb + f], s);
        sCY[dst] = s;
    }
    __syncthreads();

    // ---- Phase B2: quad descriptors — 4 consecutive-v G elements per thread ----
    float* sG = reinterpret_cast<float*>(sG4);
    if (tid < 276) {
        uint2 d = __ldg(&g_b2q[tid]);
        int gdst = d.x & 2047, cyb = (d.x >> 11) & 1023, fb = d.x >> 21;
        int di = d.y & 7, nlf = (d.y >> 3) & 7, fstr = (int)(d.y >> 6);
        float r0, r1, r2, r3;
        if (di == 1) {
            float4 f = *reinterpret_cast<const float4*>(&sFp[fb]);   // fstr==1
            float c = sCY[cyb];
            r0 = c * f.x; r1 = c * f.y; r2 = c * f.z; r3 = c * f.w;
        } else {
            float4 cy = *reinterpret_cast<const float4*>(&sCY[cyb]);
            float cy4 = (di == 5) ? sCY[cyb + 4] : 0.f;
            float4 f0 = *reinterpret_cast<const float4*>(&sFp[fb]);
            float4 f1 = *reinterpret_cast<const float4*>(&sFp[fb + fstr]);
            float4 f2 = *reinterpret_cast<const float4*>(&sFp[fb + 2 * fstr]);
            float4 f3 = *reinterpret_cast<const float4*>(&sFp[fb + 3 * fstr]);
            r0 = cy.x * f0.x + cy.y * f0.y + cy.z * f0.z;
            r1 = cy.x * f1.x + cy.y * f1.y + cy.z * f1.z;
            r2 = cy.x * f2.x + cy.y * f2.y + cy.z * f2.z;
            r3 = cy.x * f3.x + cy.y * f3.y + cy.z * f3.z;
            if (di == 5) {
                r0 += cy.w * f0.w + cy4 * sFp[fb + 4];
                r1 += cy.w * f1.w + cy4 * sFp[fb + fstr + 4];
                r2 += cy.w * f2.w + cy4 * sFp[fb + 2 * fstr + 4];
                r3 += cy.w * f3.w + cy4 * sFp[fb + 3 * fstr + 4];
            }
        }
        if (nlf == 1) {
            *reinterpret_cast<float4*>(&sG[gdst]) = make_float4(r0, r1, r2, r3);
        } else {
            sG[gdst]           = r0;
            sG[gdst + nlf]     = r1;
            sG[gdst + 2 * nlf] = r2;
            sG[gdst + 3 * nlf] = r3;
        }
    }

    // R copies must have landed (and G'' visible) before phase C
    asm volatile("cp.async.wait_group 0;");
    __syncthreads();

    // ---- Phase C: balanced split — two threads per lo=1/lo=2 output ----
    if (tid < 272) {
        float acc;
        int outi;
        if (tid < 16) {                          // lo=0 (48 FMA)
            const int u = tid;
            acc  = pairdot_s<1>(sR4, sG4,    0,   0, u, 0);
            acc += pairdot_s<1>(sR4, sG4,   80,   5, u, 0);
            acc += pairdot_s<1>(sR4, sG4,  160,  10, u, 0);
            outi = u;
        } else if (tid < 64) {                   // lo=1 h0 (64 FMA)
            const int s = tid - 16, u = s / 3, o = s - u * 3;
            acc  = pairdot_s<1>(sR4, sG4,  240,  15, u, o);
            acc += pairdot_s<3>(sR4, sG4,  320,  30, u, o);
            outi = 16 + u * 3 + o;
        } else if (tid < 112) {                  // lo=1 h1 (48 FMA)
            const int s = tid - 64, u = s / 3, o = s - u * 3;
            acc  = pairdot_s<3>(sR4, sG4,  528,  69, u, o);
            outi = 16 + u * 3 + o;
        } else if (tid < 192) {                  // lo=2 h0 (64 FMA)
            const int s = tid - 112, u = s / 5, o = s - u * 5;
            acc  = pairdot_s<1>(sR4, sG4,  736, 108, u, o);
            acc += pairdot_s<3>(sR4, sG4,  816, 133, u, o);
            outi = 64 + u * 5 + o;
        } else {                                 // lo=2 h1 (80 FMA)
            const int s = tid - 192, u = s / 5, o = s - u * 5;
            acc  = pairdot_s<5>(sR4, sG4, 1024, 198, u, o);
            outi = 64 + u * 5 + o;
        }
        atomicAdd(out + (size_t)a * FEAT + outi, acc);
    }
}

extern "C" void kernel_launch(void* const* d_in, const int* in_sizes, int n_in,
                              void* d_out, int out_size)
{
    const float* feat = (const float*)d_in[0];
    const float* rbf  = (const float*)d_in[1];
    const float* Y    = (const float*)d_in[2];
    const float* cg   = (const float*)d_in[3];
    const float* W    = (const float*)d_in[4];
    const int*   a    = (const int*)d_in[5];
    const int*   b    = (const int*)d_in[6];
    float* out = (float*)d_out;

    const int E = in_sizes[1] / EDGE_R;

    prep_kernel<<<(out_size + 255) / 256, 256>>>(out, out_size, cg, W);
    tp_kernel<<<E, NT>>>(feat, rbf, Y, a, b, out, E);
}

// round 16
// speedup vs baseline: 1.0419x; 1.0419x over previous
#include <cuda_runtime.h>
#include <cuda_bf16.h>

#define NT      352
#define FEAT    144
#define YDIM    25
#define EDGE_R  4864
#define NPATH   19

// Per-path tables (enumeration order = reference loops)
__constant__ int c_lo[NPATH]    = {0,0,0,1,1,1,1,1,1,1,2,2,2,2,2,2,2,2,2};
__constant__ int c_li[NPATH]    = {0,1,2,0,1,1,1,2,2,2,0,1,1,1,2,2,2,2,2};
__constant__ int c_lf[NPATH]    = {0,1,2,1,0,1,2,1,2,3,2,1,2,3,0,1,2,3,4};
__constant__ int c_cgoff[NPATH] = {0,1,10,35,44,53,80,125,170,245,350,375,420,495,600,625,700,825,1000};
__constant__ int c_cyoff[NPATH] = {0,1,4,9,12,21,30,39,54,69,84,89,104,119,134,159,184,209,234};
__constant__ int c_cyrow[NPATH] = {0,1,2,3,6,9,12,15,18,21,24,29,34,39,44,49,54,59,64};
__constant__ int c_b2off[NPATH] = {0,16,32,48,96,144,192,240,288,336,384,464,544,624,704,784,864,944,1024};
__constant__ int c_pair[NPATH]  = {0,1,2,3,4,4,4,5,5,5,6,7,7,7,8,8,8,8,8};
__constant__ int c_k[NPATH]     = {0,0,0,0,0,1,2,0,1,2,0,0,1,2,0,1,2,3,4};
__constant__ int c_gw[9]        = {0,20,40,60,120,276,432,532,792};
__constant__ int c_nlf9[9]      = {1,1,1,1,3,3,1,3,5};
// padded-F geometry per li: base word, v-stride
__constant__ int c_fpoff[3]     = {0,16,80};
__constant__ int c_fpstr[3]     = {1,4,8};
// df-sorted B1 placement: rank = c_b1rank[p] + j  (sorted by lf asc, path asc)
__constant__ int c_b1rank[NPATH] = {0,35,105,38,1,41,110,50,119,179,134,65,139,194,10,80,154,209,234};

// Precomputed tables (static device memory)
__device__ unsigned int   g_b1p[259];    // dst<<20 | wb<<9 | stride<<3 | lf   (df-sorted order)
__device__ unsigned int   g_b2p[1104];   // gdst<<21 | cyb<<11 | fb<<3 | di
__device__ float          g_wcgT[1225];  // TRANSPOSED: per path, df planes of (do*di)
__device__ unsigned short g_rmap[1216];  // src f4 -> padded smem f4

__device__ __forceinline__ void cp_async16(unsigned int smem_addr, const void* gptr) {
    asm volatile("cp.async.cg.shared.global [%0], [%1], 16;"
                 :: "r"(smem_addr), "l"(gptr));
}

// Padded R layout per (lo,li) pair: 16 u-rows of (4*nlf+1) float4 each.
// Word stride 16nlf+4 == 20 (mod 32) -> conflict-free across u rows.
__device__ int map_r(int G4) {
    if (G4 < 256) { int r = G4 >> 6, l = G4 & 63; return r * 80 + (l >> 2) * 5 + (l & 3); }
    else if (G4 < 448) { int l = G4 - 256, u = l / 12; return 320 + u * 13 + (l - u * 12); }
    else if (G4 < 640) { int l = G4 - 448, u = l / 12; return 528 + u * 13 + (l - u * 12); }
    else if (G4 < 704) { int l = G4 - 640; return 736 + (l >> 2) * 5 + (l & 3); }
    else if (G4 < 896) { int l = G4 - 704, u = l / 12; return 816 + u * 13 + (l - u * 12); }
    else { int l = G4 - 896, u = l / 20; return 1024 + u * 21 + (l - u * 20); }
}

// prep: zero output + build all tables (O(paths) per thread, no sorting loops)
__global__ void prep_kernel(float* out, int n,
                            const float* __restrict__ cg, const float* __restrict__ W) {
    int t = blockIdx.x * blockDim.x + threadIdx.x;
    if (t < n) out[t] = 0.f;
    if (t < 259) {
        int p = 0;
        for (int q = 1; q < NPATH; ++q) if (t >= c_cyoff[q]) p = q;
        int j = t - c_cyoff[p];
        int li = c_li[p], lf = c_lf[p], lo = c_lo[p];
        int di = 2 * li + 1, doo = 2 * lo + 1;
        int o = j / di, i = j - o * di;
        unsigned dst = (unsigned)((c_cyrow[p] + o) * 8 + i);
        unsigned str = (unsigned)(doo * di);
        unsigned desc = (dst << 20) | ((unsigned)(c_cgoff[p] + j) << 9)
                      | (str << 3) | (unsigned)lf;
        g_b1p[c_b1rank[p] + j] = desc;      // df-sorted placement, O(1)
    }
    if (t < 1104) {
        int p = 0;
        for (int q = 1; q < NPATH; ++q) if (t >= c_b2off[q]) p = q;
        int j = t - c_b2off[p];
        int lo = c_lo[p], li = c_li[p];
        int doo = 2 * lo + 1, di = 2 * li + 1;
        int v = j / doo, o = j - v * doo;
        int pr = c_pair[p], nlf = c_nlf9[pr];
        unsigned gdst = (unsigned)(c_gw[pr] + o * (16 * nlf + 4) + v * nlf + c_k[p]);
        unsigned cyb  = (unsigned)((c_cyrow[p] + o) * 8);
        unsigned fb   = (unsigned)(c_fpoff[li] + v * c_fpstr[li]);
        g_b2p[t] = (gdst << 21) | (cyb << 11) | (fb << 3) | (unsigned)di;
    }
    if (t < 1225) {   // transposed W-folded cg
        int p = 0;
        for (int q = 1; q < NPATH; ++q) if (t >= c_cgoff[q]) p = q;
        int local = t - c_cgoff[p];
        int lo = c_lo[p], li = c_li[p], lf = c_lf[p];
        int n2 = (2 * lo + 1) * (2 * li + 1), df = 2 * lf + 1;
        int f = local / n2, j = local - f * n2;
        g_wcgT[t] = cg[c_cgoff[p] + j * df + f] * W[p];
    }
    if (t < 1216) g_rmap[t] = (unsigned short)map_r(t);
}

// acc += R_row . G_row over 4*NLF float4 from padded smem (conflict-free, broadcast-dedup)
template<int NLF>
__device__ __forceinline__ float pairdot_s(const float4* __restrict__ sR4,
                                           const float4* __restrict__ sG4,
                                           int rf4, int gf4, int u, int o) {
    const float4* r = sR4 + rf4 + u * (4 * NLF + 1);
    const float4* g = sG4 + gf4 + o * (4 * NLF + 1);
    float a0 = 0.f, a1 = 0.f, a2 = 0.f, a3 = 0.f;
    #pragma unroll
    for (int j = 0; j < 4 * NLF; ++j) {
        float4 A = r[j];
        float4 B = g[j];
        a0 = fmaf(A.x, B.x, a0);
        a1 = fmaf(A.y, B.y, a1);
        a2 = fmaf(A.z, B.z, a2);
        a3 = fmaf(A.w, B.w, a3);
    }
    return (a0 + a1) + (a2 + a3);
}

__global__ void __launch_bounds__(NT, 5)
tp_kernel(const float* __restrict__ feat, const float* __restrict__ rbf,
          const float* __restrict__ Y,    const int* __restrict__ aidx,
          const int* __restrict__ bidx,   float* __restrict__ out, int E)
{
    __shared__ float4 sR4[1360];     // padded R (21.8 KB)
    __shared__ float4 sG4[304];      // padded/interleaved W*G''
    __shared__ float4 sCY4[138];     // padded CY: 69 rows x 8 words
    __shared__ float4 sFp4[52];      // padded F: 208 words (li strides 1/4/8)
    __shared__ float  sY[32];

    float* sCY = reinterpret_cast<float*>(sCY4);
    float* sFp = reinterpret_cast<float*>(sFp4);

    const int e = blockIdx.x, tid = threadIdx.x;
    const int a = aidx[e];
    const int b = bidx[e];

    // ---- Phase A0: fire ALL R copies async (DRAM latency overlaps B1/B2) ----
    {
        const float4* r4 = reinterpret_cast<const float4*>(rbf + (size_t)e * EDGE_R);
        const unsigned int sR_base = (unsigned int)__cvta_generic_to_shared(sR4);
        #pragma unroll
        for (int i = 0; i < 4; ++i) {
            int t = tid + i * NT;
            if (t < 1216)
                cp_async16(sR_base + (unsigned)__ldg(&g_rmap[t]) * 16u, r4 + t);
        }
        asm volatile("cp.async.commit_group;");
    }

    // ---- Phase A1: F gather into PADDED layout + Y ----
    {
        const float* Fr = feat + (size_t)b * FEAT;
        if (tid < 208) {
            int w = tid;
            float val = 0.f;
            bool wr = true;
            if (w < 16) {
                val = __ldg(&Fr[w]);
            } else if (w < 80) {
                int v = (w - 16) >> 2, i = (w - 16) & 3;
                if (i < 3) val = __ldg(&Fr[16 + v * 3 + i]); else wr = false;
            } else {
                int v = (w - 80) >> 3, i = (w - 80) & 7;
                if (i < 5) val = __ldg(&Fr[64 + v * 5 + i]); else wr = false;
            }
            if (wr) sFp[w] = val;
        }
        if (tid >= 224 && tid < 224 + YDIM)
            sY[tid - 224] = __ldg(&Y[(size_t)e * YDIM + (tid - 224)]);
    }
    __syncthreads();

    // ---- Phase B1: CY[dst] = sum_f wcgT[wb + f*str] * Y[lf*lf+f]
    //      df-sorted order -> warps have uniform df, no max-df penalty ----
    if (tid < 259) {
        unsigned d = __ldg(&g_b1p[tid]);
        int lf = d & 7, str = (d >> 3) & 63, wb = (d >> 9) & 0x7FF, dst = d >> 20;
        int df = 2 * lf + 1, yb = lf * lf;
        float s = 0.f;
        for (int f = 0; f < df; ++f)
            s = fmaf(__ldg(&g_wcgT[wb + f * str]), sY[yb + f], s);
        sCY[dst] = s;
    }
    __syncthreads();

    // ---- Phase B2: G''[gdst] = CY_row . F_row (vectorized LDS.128) ----
    float* sG = reinterpret_cast<float*>(sG4);
    for (int t = tid; t < 1104; t += NT) {
        unsigned d = __ldg(&g_b2p[t]);
        int di = d & 7, fb = (d >> 3) & 255, cyb = (d >> 11) & 1023, gdst = d >> 21;
        float s;
        if (di == 1) {
            s = sCY[cyb] * sFp[fb];
        } else {
            float4 cy = *reinterpret_cast<const float4*>(&sCY[cyb]);
            float4 fv = *reinterpret_cast<const float4*>(&sFp[fb]);
            s = cy.x * fv.x + cy.y * fv.y + cy.z * fv.z;
            if (di == 5)
                s += cy.w * fv.w + sCY[cyb + 4] * sFp[fb + 4];
        }
        sG[gdst] = s;
    }

    // R copies must have landed (and G'' visible) before phase C
    asm volatile("cp.async.wait_group 0;");
    __syncthreads();

    // ---- Phase C: WARP-ALIGNED classes (idle-lane padding -> one body per warp) ----
    // w0:        tids   0- 15  lo=0        (16 idle in w0)
    // w1-2:      tids  32- 79  lo=1 h0     (80-95 idle)
    // w3-4:      tids  96-143  lo=1 h1     (144-159 idle)
    // w5-7:      tids 160-239  lo=2 h0     (240-255 idle)
    // w8-10:     tids 256-335  lo=2 h1     (336-351 idle)
    {
        float acc = 0.f;
        int outi = -1;
        if (tid < 32) {
            if (tid < 16) {                      // lo=0 (48 FMA)
                const int u = tid;
                acc  = pairdot_s<1>(sR4, sG4,    0,   0, u, 0);
                acc += pairdot_s<1>(sR4, sG4,   80,   5, u, 0);
                acc += pairdot_s<1>(sR4, sG4,  160,  10, u, 0);
                outi = u;
            }
        } else if (tid < 96) {
            const int s = tid - 32;
            if (s < 48) {                        // lo=1 h0 (64 FMA)
                const int u = s / 3, o = s - u * 3;
                acc  = pairdot_s<1>(sR4, sG4,  240,  15, u, o);
                acc += pairdot_s<3>(sR4, sG4,  320,  30, u, o);
                outi = 16 + u * 3 + o;
            }
        } else if (tid < 160) {
            const int s = tid - 96;
            if (s < 48) {                        // lo=1 h1 (48 FMA)
                const int u = s / 3, o = s - u * 3;
                acc  = pairdot_s<3>(sR4, sG4,  528,  69, u, o);
                outi = 16 + u * 3 + o;
            }
        } else if (tid < 256) {
            const int s = tid - 160;
            if (s < 80) {                        // lo=2 h0 (64 FMA)
                const int u = s / 5, o = s - u * 5;
                acc  = pairdot_s<1>(sR4, sG4,  736, 108, u, o);
                acc += pairdot_s<3>(sR4, sG4,  816, 133, u, o);
                outi = 64 + u * 5 + o;
            }
        } else {
            const int s = tid - 256;
            if (s < 80) {                        // lo=2 h1 (80 FMA)
                const int u = s / 5, o = s - u * 5;
                acc  = pairdot_s<5>(sR4, sG4, 1024, 198, u, o);
                outi = 64 + u * 5 + o;
            }
        }
        if (outi >= 0)
            atomicAdd(out + (size_t)a * FEAT + outi, acc);
    }
}

extern "C" void kernel_launch(void* const* d_in, const int* in_sizes, int n_in,
                              void* d_out, int out_size)
{
    const float* feat = (const float*)d_in[0];
    const float* rbf  = (const float*)d_in[1];
    const float* Y    = (const float*)d_in[2];
    const float* cg   = (const float*)d_in[3];
    const float* W    = (const float*)d_in[4];
    const int*   a    = (const int*)d_in[5];
    const int*   b    = (const int*)d_in[6];
    float* out = (float*)d_out;

    const int E = in_sizes[1] / EDGE_R;

    prep_kernel<<<(out_size + 255) / 256, 256>>>(out, out_size, cg, W);
    tp_kernel<<<E, NT>>>(feat, rbf, Y, a, b, out, E);
}

// round 17
// speedup vs baseline: 1.1285x; 1.0831x over previous
#include <cuda_runtime.h>
#include <cuda_bf16.h>

#define NT      288
#define FEAT    144
#define YDIM    25
#define EDGE_R  4864
#define NPATH   19

// Per-path tables (enumeration order = reference loops)
__constant__ int c_lo[NPATH]    = {0,0,0,1,1,1,1,1,1,1,2,2,2,2,2,2,2,2,2};
__constant__ int c_li[NPATH]    = {0,1,2,0,1,1,1,2,2,2,0,1,1,1,2,2,2,2,2};
__constant__ int c_lf[NPATH]    = {0,1,2,1,0,1,2,1,2,3,2,1,2,3,0,1,2,3,4};
__constant__ int c_cgoff[NPATH] = {0,1,10,35,44,53,80,125,170,245,350,375,420,495,600,625,700,825,1000};
__constant__ int c_cyoff[NPATH] = {0,1,4,9,12,21,30,39,54,69,84,89,104,119,134,159,184,209,234};
__constant__ int c_cyrow[NPATH] = {0,1,2,3,6,9,12,15,18,21,24,29,34,39,44,49,54,59,64};
__constant__ int c_b2off[NPATH] = {0,16,32,48,96,144,192,240,288,336,384,464,544,624,704,784,864,944,1024};
__constant__ int c_pair[NPATH]  = {0,1,2,3,4,4,4,5,5,5,6,7,7,7,8,8,8,8,8};
__constant__ int c_k[NPATH]     = {0,0,0,0,0,1,2,0,1,2,0,0,1,2,0,1,2,3,4};
__constant__ int c_nlf9[9]      = {1,1,1,1,3,3,1,3,5};
// CONCATENATED padded G'' layout: word base + o-stride (words) per pair
__constant__ int c_gw2[9]       = {0,16,32,52,68,256,412,428,752};
__constant__ int c_gos[9]       = {52,52,52,68,68,52,68,68,84};
// padded-F geometry per li: base word, v-stride
__constant__ int c_fpoff[3]     = {0,16,80};
__constant__ int c_fpstr[3]     = {1,4,8};
// df-sorted B1 placement: rank = c_b1rank[p] + j  (sorted by lf asc, path asc)
__constant__ int c_b1rank[NPATH] = {0,35,105,38,1,41,110,50,119,179,134,65,139,194,10,80,154,209,234};

// Precomputed tables (static device memory)
__device__ unsigned int   g_b1p[259];    // dst<<20 | wb<<9 | stride<<3 | lf   (df-sorted order)
__device__ unsigned int   g_b2p[1104];   // gdst<<21 | cyb<<11 | fb<<3 | di
__device__ float          g_wcgT[1225];  // TRANSPOSED: per path, df planes of (do*di)
__device__ unsigned short g_rmap[1216];  // src f4 -> padded CONCATENATED smem f4

__device__ __forceinline__ void cp_async16(unsigned int smem_addr, const void* gptr) {
    asm volatile("cp.async.cg.shared.global [%0], [%1], 16;"
                 :: "r"(smem_addr), "l"(gptr));
}

// CONCATENATED padded R layout (f4 units):
//  lo0   : 16 u-rows of 13 f4 ([p00|p01|p02]+pad)      base    0
//  lo1h0 : 16 u-rows of 17 f4 ([p10|p11]+pad)          base  208
//  lo1h1 : 16 u-rows of 13 f4 ([p12]+pad)              base  480
//  lo2h0 : 16 u-rows of 17 f4 ([p20|p21]+pad)          base  688
//  lo2h1 : 16 u-rows of 21 f4 ([p22]+pad)              base  960   (total 1296)
// Strides 13/17/21 f4 = 52/68/84 words == 20/4/20 mod 32 -> conflict-free across rows.
__device__ int map_r2(int t) {
    if (t < 192)      { int p = t >> 6, l = t & 63; return (l >> 2) * 13 + p * 4 + (l & 3); }
    else if (t < 256) { int l = t - 192; return 208 + (l >> 2) * 17 + (l & 3); }
    else if (t < 448) { int l = t - 256; int u = l / 12; return 208 + u * 17 + 4 + (l - u * 12); }
    else if (t < 640) { int l = t - 448; int u = l / 12; return 480 + u * 13 + (l - u * 12); }
    else if (t < 704) { int l = t - 640; return 688 + (l >> 2) * 17 + (l & 3); }
    else if (t < 896) { int l = t - 704; int u = l / 12; return 688 + u * 17 + 4 + (l - u * 12); }
    else              { int l = t - 896; int u = l / 20; return 960 + u * 21 + (l - u * 20); }
}

// prep: zero output + build all tables (O(paths) per thread, no sorting loops)
__global__ void prep_kernel(float* out, int n,
                            const float* __restrict__ cg, const float* __restrict__ W) {
    int t = blockIdx.x * blockDim.x + threadIdx.x;
    if (t < n) out[t] = 0.f;
    if (t < 259) {
        int p = 0;
        for (int q = 1; q < NPATH; ++q) if (t >= c_cyoff[q]) p = q;
        int j = t - c_cyoff[p];
        int li = c_li[p], lf = c_lf[p], lo = c_lo[p];
        int di = 2 * li + 1, doo = 2 * lo + 1;
        int o = j / di, i = j - o * di;
        unsigned dst = (unsigned)((c_cyrow[p] + o) * 8 + i);
        unsigned str = (unsigned)(doo * di);
        unsigned desc = (dst << 20) | ((unsigned)(c_cgoff[p] + j) << 9)
                      | (str << 3) | (unsigned)lf;
        g_b1p[c_b1rank[p] + j] = desc;      // df-sorted placement, O(1)
    }
    if (t < 1104) {
        int p = 0;
        for (int q = 1; q < NPATH; ++q) if (t >= c_b2off[q]) p = q;
        int j = t - c_b2off[p];
        int lo = c_lo[p], li = c_li[p];
        int doo = 2 * lo + 1, di = 2 * li + 1;
        int v = j / doo, o = j - v * doo;
        int pr = c_pair[p], nlf = c_nlf9[pr];
        unsigned gdst = (unsigned)(c_gw2[pr] + o * c_gos[pr] + v * nlf + c_k[p]);
        unsigned cyb  = (unsigned)((c_cyrow[p] + o) * 8);
        unsigned fb   = (unsigned)(c_fpoff[li] + v * c_fpstr[li]);
        g_b2p[t] = (gdst << 21) | (cyb << 11) | (fb << 3) | (unsigned)di;
    }
    if (t < 1225) {   // transposed W-folded cg
        int p = 0;
        for (int q = 1; q < NPATH; ++q) if (t >= c_cgoff[q]) p = q;
        int local = t - c_cgoff[p];
        int lo = c_lo[p], li = c_li[p], lf = c_lf[p];
        int n2 = (2 * lo + 1) * (2 * li + 1), df = 2 * lf + 1;
        int f = local / n2, j = local - f * n2;
        g_wcgT[t] = cg[c_cgoff[p] + j * df + f] * W[p];
    }
    if (t < 1216) g_rmap[t] = (unsigned short)map_r2(t);
}

// acc = sum over N4 float4 of R_row . G_row (both padded smem, conflict-free)
template<int N4>
__device__ __forceinline__ float dotN(const float4* __restrict__ r,
                                      const float4* __restrict__ g) {
    float a0 = 0.f, a1 = 0.f, a2 = 0.f, a3 = 0.f;
    #pragma unroll
    for (int j = 0; j < N4; ++j) {
        float4 A = r[j];
        float4 B = g[j];
        a0 = fmaf(A.x, B.x, a0);
        a1 = fmaf(A.y, B.y, a1);
        a2 = fmaf(A.z, B.z, a2);
        a3 = fmaf(A.w, B.w, a3);
    }
    return (a0 + a1) + (a2 + a3);
}

__global__ void __launch_bounds__(NT, 7)
tp_kernel(const float* __restrict__ feat, const float* __restrict__ rbf,
          const float* __restrict__ Y,    const int* __restrict__ aidx,
          const int* __restrict__ bidx,   float* __restrict__ out, int E)
{
    __shared__ float4 sR4[1296];     // padded concatenated R (20.7 KB)
    __shared__ float4 sG4[296];      // padded concatenated W*G'' (293 used)
    __shared__ float4 sCY4[138];     // padded CY: 69 rows x 8 words
    __shared__ float4 sFp4[52];      // padded F: 208 words (li strides 1/4/8)
    __shared__ float  sY[32];

    float* sCY = reinterpret_cast<float*>(sCY4);
    float* sFp = reinterpret_cast<float*>(sFp4);

    const int e = blockIdx.x, tid = threadIdx.x;
    const int a = aidx[e];
    const int b = bidx[e];

    // ---- Phase A0: fire ALL R copies async (DRAM latency overlaps B1/B2) ----
    {
        const float4* r4 = reinterpret_cast<const float4*>(rbf + (size_t)e * EDGE_R);
        const unsigned int sR_base = (unsigned int)__cvta_generic_to_shared(sR4);
        #pragma unroll
        for (int i = 0; i < 5; ++i) {
            int t = tid + i * NT;
            if (t < 1216)
                cp_async16(sR_base + (unsigned)__ldg(&g_rmap[t]) * 16u, r4 + t);
        }
        asm volatile("cp.async.commit_group;");
    }

    // ---- Phase A1: F gather into PADDED layout + Y ----
    {
        const float* Fr = feat + (size_t)b * FEAT;
        if (tid < 208) {
            int w = tid;
            float val = 0.f;
            bool wr = true;
            if (w < 16) {
                val = __ldg(&Fr[w]);
            } else if (w < 80) {
                int v = (w - 16) >> 2, i = (w - 16) & 3;
                if (i < 3) val = __ldg(&Fr[16 + v * 3 + i]); else wr = false;
            } else {
                int v = (w - 80) >> 3, i = (w - 80) & 7;
                if (i < 5) val = __ldg(&Fr[64 + v * 5 + i]); else wr = false;
            }
            if (wr) sFp[w] = val;
        }
        if (tid >= 224 && tid < 224 + YDIM)
            sY[tid - 224] = __ldg(&Y[(size_t)e * YDIM + (tid - 224)]);
    }
    __syncthreads();

    // ---- Phase B1: CY[dst] = sum_f wcgT[wb + f*str] * Y[lf*lf+f]
    //      df-sorted order -> warps have uniform df, no max-df penalty ----
    if (tid < 259) {
        unsigned d = __ldg(&g_b1p[tid]);
        int lf = d & 7, str = (d >> 3) & 63, wb = (d >> 9) & 0x7FF, dst = d >> 20;
        int df = 2 * lf + 1, yb = lf * lf;
        float s = 0.f;
        for (int f = 0; f < df; ++f)
            s = fmaf(__ldg(&g_wcgT[wb + f * str]), sY[yb + f], s);
        sCY[dst] = s;
    }
    __syncthreads();

    // ---- Phase B2: G''[gdst] = CY_row . F_row (vectorized LDS.128) ----
    float* sG = reinterpret_cast<float*>(sG4);
    for (int t = tid; t < 1104; t += NT) {
        unsigned d = __ldg(&g_b2p[t]);
        int di = d & 7, fb = (d >> 3) & 255, cyb = (d >> 11) & 1023, gdst = d >> 21;
        float s;
        if (di == 1) {
            s = sCY[cyb] * sFp[fb];
        } else {
            float4 cy = *reinterpret_cast<const float4*>(&sCY[cyb]);
            float4 fv = *reinterpret_cast<const float4*>(&sFp[fb]);
            s = cy.x * fv.x + cy.y * fv.y + cy.z * fv.z;
            if (di == 5)
                s += cy.w * fv.w + sCY[cyb + 4] * sFp[fb + 4];
        }
        sG[gdst] = s;
    }

    // R copies must have landed (and G'' visible) before phase C
    asm volatile("cp.async.wait_group 0;");
    __syncthreads();

    // ---- Phase C: three warp-aligned uniform classes (one body per warp) ----
    //  tids   0- 63 : len12 — lo0 full (16) + lo1h1 partial (48), both 48 FMA
    //  tids  64-191 : len16 — lo1h0 partial (48) + lo2h0 partial (80), 64 FMA
    //  tids 192-287 : len20 — lo2h1 partial (80 active + 16 idle), 80 FMA
    {
        float acc;
        int outi;
        if (tid < 64) {
            int rb, gb;
            if (tid < 16) { rb = tid * 13;                gb = 0;            outi = tid; }
            else { int s = tid - 16, u = s / 3, o = s - u * 3;
                   rb = 480 + u * 13;                      gb = 64 + o * 13;  outi = 16 + u * 3 + o; }
            acc = dotN<12>(sR4 + rb, sG4 + gb);
            atomicAdd(out + (size_t)a * FEAT + outi, acc);
        } else if (tid < 192) {
            int s = tid - 64, rb, gb;
            if (s < 48) { int u = s / 3, o = s - u * 3;
                          rb = 208 + u * 17;               gb = 13 + o * 17;  outi = 16 + u * 3 + o; }
            else { int s2 = s - 48, u = s2 / 5, o = s2 - u * 5;
                          rb = 688 + u * 17;               gb = 103 + o * 17; outi = 64 + u * 5 + o; }
            acc = dotN<16>(sR4 + rb, sG4 + gb);
            atomicAdd(out + (size_t)a * FEAT + outi, acc);
        } else {
            int s = tid - 192;
            if (s < 80) {
                int u = s / 5, o = s - u * 5;
                acc = dotN<20>(sR4 + 960 + u * 21, sG4 + 188 + o * 21);
                outi = 64 + u * 5 + o;
                atomicAdd(out + (size_t)a * FEAT + outi, acc);
            }
        }
    }
}

extern "C" void kernel_launch(void* const* d_in, const int* in_sizes, int n_in,
                              void* d_out, int out_size)
{
    const float* feat = (const float*)d_in[0];
    const float* rbf  = (const float*)d_in[1];
    const float* Y    = (const float*)d_in[2];
    const float* cg   = (const float*)d_in[3];
    const float* W    = (const float*)d_in[4];
    const int*   a    = (const int*)d_in[5];
    const int*   b    = (const int*)d_in[6];
    float* out = (float*)d_out;

    const int E = in_sizes[1] / EDGE_R;

    prep_kernel<<<(out_size + 255) / 256, 256>>>(out, out_size, cg, W);
    tp_kernel<<<E, NT>>>(feat, rbf, Y, a, b, out, E);
}